// round 14
// baseline (speedup 1.0000x reference)
#include <cuda_runtime.h>
#include <cuda_fp16.h>
#include <cstdint>

// Problem constants
#define N1_SRC 495616
#define N1_DST 45056
#define E1     450560
#define N2_SRC 45056
#define N2_DST 4096
#define E2     40960
#define D      512
#define DOUT   256

// ---------------- device scratch ----------------
__device__ __half g_h1h[(size_t)N1_DST * D];          // layer-1 output (fp16, compact)
__device__ __half g_a1h[(size_t)N1_DST * D];          // layer-1 A (fp16, compact)
__device__ __half g_a2h[(size_t)N2_DST * D];          // layer-2 A (single fp16)
__device__ __half g_w1hi[(size_t)D * D];              // W1^T [N=512,K=512] fp16
__device__ __half g_w2hi[(size_t)DOUT * D];           // W2^T [N=256,K=512] fp16

// cnt1 | cnt2 | used  — zero-invariant restored by scan_all_k (no memset launch)
__device__ int g_cnt[N1_DST + N2_DST + N1_DST];
__device__ int g_cur[N1_DST + N2_DST];
__device__ int g_off1[N1_DST + 1];
__device__ int g_srt1[E1];
__device__ int g_off2[N2_DST + 1];
__device__ int g_srt2[E2];                             // stores REMAPPED src ids
__device__ int g_remap[N1_DST + 1];
__device__ int g_ulist[N1_DST];
__device__ int g_ucnt[1];

// ---------------- PTX helpers (base-target safe) ----------------
__device__ __forceinline__ uint32_t smem_u32(const void* p) {
    uint32_t a;
    asm("{ .reg .u64 t; cvta.to.shared.u64 t, %1; cvt.u32.u64 %0, t; }" : "=r"(a) : "l"(p));
    return a;
}
__device__ __forceinline__ void cp16(uint32_t s, const void* g) {
    asm volatile("cp.async.cg.shared.global [%0], [%1], 16;" :: "r"(s), "l"(g));
}
__device__ __forceinline__ void cp_commit() {
    asm volatile("cp.async.commit_group;" ::: "memory");
}
template <int N>
__device__ __forceinline__ void cp_wait() {
    asm volatile("cp.async.wait_group %0;" :: "n"(N) : "memory");
}
__device__ __forceinline__ void ldm_x4(uint32_t* r, uint32_t addr) {
    asm volatile("ldmatrix.sync.aligned.m8n8.x4.shared.b16 {%0,%1,%2,%3}, [%4];"
                 : "=r"(r[0]), "=r"(r[1]), "=r"(r[2]), "=r"(r[3]) : "r"(addr));
}
// D += A(f16) * B(f16), m16n8k16, fp32 accum
__device__ __forceinline__ void mma_f16(float* c, const uint32_t* a, const uint32_t* b) {
    asm volatile(
        "mma.sync.aligned.m16n8k16.row.col.f32.f16.f16.f32 "
        "{%0,%1,%2,%3}, {%4,%5,%6,%7}, {%8,%9}, {%0,%1,%2,%3};"
        : "+f"(c[0]), "+f"(c[1]), "+f"(c[2]), "+f"(c[3])
        : "r"(a[0]), "r"(a[1]), "r"(a[2]), "r"(a[3]), "r"(b[0]), "r"(b[1]));
}

// ---------------- fused prep: hist + used-marks + weight conversion (R12 interleaved form) ----------------
#define PREP_N (E1 + E2 + N2_DST + D * D + DOUT * D)

__global__ void prep_k(const int* __restrict__ ed1, const int* __restrict__ ed2,
                       const int* __restrict__ es2, int* __restrict__ cnt,
                       const float* __restrict__ W1, __half* __restrict__ t1,
                       const float* __restrict__ W2, __half* __restrict__ t2) {
    int* used = cnt + (N1_DST + N2_DST);
    int i = blockIdx.x * blockDim.x + threadIdx.x;
    if (i < E1) {
        atomicAdd(&cnt[ed1[i]], 1);
    } else if (i < E1 + E2) {
        int j = i - E1;
        atomicAdd(&cnt[N1_DST + ed2[j]], 1);
        used[es2[j]] = 1;                 // benign race, deterministic
    } else if (i < E1 + E2 + N2_DST) {
        used[i - E1 - E2] = 1;            // self rows 0..4095
    } else {
        int j = i - (E1 + E2 + N2_DST);
        if (j < D * D) {
            int n = j / D, k = j - n * D;
            t1[j] = __float2half_rn(W1[(size_t)k * D + n]);
        } else if (j < D * D + DOUT * D) {
            j -= D * D;
            int n = j / D, k = j - n * D;
            t2[j] = __float2half_rn(W2[(size_t)k * DOUT + n]);
        }
    }
}

// block 0: cnt1->off1/cur ; block 1: cnt2->off2/cur+N1 ; block 2: used->remap,+ucnt,+ulist
// 4 elements per thread; zeroes cnt behind itself (restores invariant for next replay)
__global__ void scan_all_k(int* __restrict__ cnt, int* __restrict__ cur,
                           int* __restrict__ off1, int* __restrict__ off2,
                           int* __restrict__ remap, int* __restrict__ ucnt,
                           int* __restrict__ ulist) {
    int* c; int* cu; int* off; int n;
    if (blockIdx.x == 0)      { c = cnt;                    cu = cur;           off = off1;  n = N1_DST; }
    else if (blockIdx.x == 1) { c = cnt + N1_DST;           cu = cur + N1_DST;  off = off2;  n = N2_DST; }
    else                      { c = cnt + N1_DST + N2_DST;  cu = nullptr;       off = remap; n = N1_DST; }

    __shared__ int wsum[32];
    __shared__ int carry_s;
    int tid = threadIdx.x, lane = tid & 31, w = tid >> 5;
    bool is_used_blk = (blockIdx.x == 2);
    if (tid == 0) carry_s = 0;
    __syncthreads();
    for (int base = 0; base < n; base += 4096) {
        int i = base + tid * 4;
        int4 v = *(const int4*)&c[i];
        *(int4*)&c[i] = make_int4(0, 0, 0, 0);        // restore zero-invariant
        int s = v.x + v.y + v.z + v.w;
        int x = s;
#pragma unroll
        for (int st = 1; st < 32; st <<= 1) {
            int t = __shfl_up_sync(0xFFFFFFFFu, x, st);
            if (lane >= st) x += t;
        }
        if (lane == 31) wsum[w] = x;
        __syncthreads();
        if (w == 0) {
            int y = wsum[lane];
#pragma unroll
            for (int st = 1; st < 32; st <<= 1) {
                int t = __shfl_up_sync(0xFFFFFFFFu, y, st);
                if (lane >= st) y += t;
            }
            wsum[lane] = y;
        }
        __syncthreads();
        int excl = carry_s + (w ? wsum[w - 1] : 0) + x - s;   // exclusive prefix of item 0
        int4 o;
        o.x = excl;
        o.y = excl + v.x;
        o.z = excl + v.x + v.y;
        o.w = excl + v.x + v.y + v.z;
        *(int4*)&off[i] = o;
        if (cu) *(int4*)&cu[i] = o;
        if (is_used_blk) {                // build compact used-node list in place
            if (v.x) ulist[o.x] = i;
            if (v.y) ulist[o.y] = i + 1;
            if (v.z) ulist[o.z] = i + 2;
            if (v.w) ulist[o.w] = i + 3;
        }
        __syncthreads();
        if (tid == 1023) carry_s = excl + s;
        __syncthreads();
    }
    if (threadIdx.x == 0) {
        off[n] = carry_s;
        if (is_used_blk) ucnt[0] = carry_s;
    }
}

// scatter both edge lists; layer-1 edges of UNUSED dst nodes are skipped (never read);
// layer-2 sources remapped into compact h1 space
__global__ void scatter_all_k(const int* __restrict__ es1, const int* __restrict__ ed1,
                              const int* __restrict__ es2, const int* __restrict__ ed2,
                              int* __restrict__ cur, const int* __restrict__ remap,
                              int* __restrict__ srt1, int* __restrict__ srt2) {
    int i = blockIdx.x * blockDim.x + threadIdx.x;
    if (i < E1) {
        int d = ed1[i];
        if (remap[d + 1] > remap[d]) {    // dst is used downstream
            int p = atomicAdd(&cur[d], 1);
            srt1[p] = es1[i];
        }
    } else if (i < E1 + E2) {
        int j = i - E1;
        int p = atomicAdd(&cur[N1_DST + ed2[j]], 1);
        srt2[p] = remap[es2[j]];
    }
}

// ---------------- layer-1 aggregation: only USED nodes, compact fp16 out ----------------
__global__ void __launch_bounds__(128)
agg1_k(const float* __restrict__ feat, const int* __restrict__ off,
       const int* __restrict__ srt, const int* __restrict__ ulist,
       const int* __restrict__ ucnt, __half* __restrict__ ahi) {
    int b = blockIdx.x;
    if (b >= ucnt[0]) return;
    int node = ulist[b];
    int t = threadIdx.x;                  // covers cols t*4 .. t*4+3
    const float4* fp = (const float4*)feat;
    int bg = off[node], e = off[node + 1];

    float4 acc = fp[(size_t)node * (D / 4) + t];
    int j = bg;
    for (; j + 3 < e; j += 4) {
        int s0 = srt[j], s1 = srt[j + 1], s2 = srt[j + 2], s3 = srt[j + 3];
        float4 v0 = fp[(size_t)s0 * (D / 4) + t];
        float4 v1 = fp[(size_t)s1 * (D / 4) + t];
        float4 v2 = fp[(size_t)s2 * (D / 4) + t];
        float4 v3 = fp[(size_t)s3 * (D / 4) + t];
        acc.x += v0.x + v1.x + v2.x + v3.x;
        acc.y += v0.y + v1.y + v2.y + v3.y;
        acc.z += v0.z + v1.z + v2.z + v3.z;
        acc.w += v0.w + v1.w + v2.w + v3.w;
    }
    for (; j < e; j++) {
        int s0 = srt[j];
        float4 v0 = fp[(size_t)s0 * (D / 4) + t];
        acc.x += v0.x; acc.y += v0.y; acc.z += v0.z; acc.w += v0.w;
    }
    float sc = 1.0f / (float)(e - bg + 1);
    __half2 p01 = __floats2half2_rn(acc.x * sc, acc.y * sc);
    __half2 p23 = __floats2half2_rn(acc.z * sc, acc.w * sc);
    uint2 o;
    o.x = *(uint32_t*)&p01;
    o.y = *(uint32_t*)&p23;
    ((uint2*)ahi)[(size_t)b * (D / 4) + t] = o;       // compact row b
}

// ---------------- layer-2 aggregation: fp16 gather (compact h1) -> single fp16 ----------------
__global__ void __launch_bounds__(128)
agg2_k(const __half* __restrict__ feat, const int* __restrict__ off,
       const int* __restrict__ srt, const int* __restrict__ remap,
       __half* __restrict__ ah) {
    int node = blockIdx.x;
    int t = threadIdx.x;                  // covers cols t*4 .. t*4+3
    const uint2* fp = (const uint2*)feat;
    int b = off[node], e = off[node + 1];

    uint2 sv = fp[(size_t)remap[node] * (D / 4) + t];   // self row (remapped)
    float2 f01 = __half22float2(*(__half2*)&sv.x);
    float2 f23 = __half22float2(*(__half2*)&sv.y);
    float a0 = f01.x, a1 = f01.y, a2 = f23.x, a3 = f23.y;

    int j = b;
    for (; j + 1 < e; j += 2) {
        uint2 v0 = fp[(size_t)srt[j] * (D / 4) + t];
        uint2 v1 = fp[(size_t)srt[j + 1] * (D / 4) + t];
        float2 u0 = __half22float2(*(__half2*)&v0.x);
        float2 u1 = __half22float2(*(__half2*)&v0.y);
        float2 w0 = __half22float2(*(__half2*)&v1.x);
        float2 w1 = __half22float2(*(__half2*)&v1.y);
        a0 += u0.x + w0.x; a1 += u0.y + w0.y;
        a2 += u1.x + w1.x; a3 += u1.y + w1.y;
    }
    if (j < e) {
        uint2 v0 = fp[(size_t)srt[j] * (D / 4) + t];
        float2 u0 = __half22float2(*(__half2*)&v0.x);
        float2 u1 = __half22float2(*(__half2*)&v0.y);
        a0 += u0.x; a1 += u0.y; a2 += u1.x; a3 += u1.y;
    }
    float sc = 1.0f / (float)(e - b + 1);
    __half2 p01 = __floats2half2_rn(a0 * sc, a1 * sc);
    __half2 p23 = __floats2half2_rn(a2 * sc, a3 * sc);
    uint2 o;
    o.x = *(uint32_t*)&p01;
    o.y = *(uint32_t*)&p23;
    ((uint2*)ah)[(size_t)node * (D / 4) + t] = o;
}

// ---------------- HMMA fp16 GEMM (templated) ----------------
// C = Ah*Bh + bias, opt relu. HOUT: fp16 out. mcount: optional M early-exit bound.
#define ROWB 80

template <int BM, int BN, int TM, int TN, bool HOUT>
__global__ void __launch_bounds__(TM * TN * 32, 1)
gemm_hmma_k(const __half* __restrict__ Ah, const __half* __restrict__ Bh,
            const float* __restrict__ bias, void* __restrict__ Cv,
            int ldc, int relu, const int* __restrict__ mcount) {
    constexpr int THREADS = TM * TN * 32;
    constexpr int WM = BM / TM;
    constexpr int WN = BN / TN;
    constexpr int MT = WM / 16;
    constexpr int NG = WN / 16;
    constexpr int NT = WN / 8;
    constexpr int TOTROWS = BM + BN;
    constexpr int STAGE = TOTROWS * ROWB;
    constexpr int OPS = TOTROWS * 4 / THREADS;

    int m0 = blockIdx.y * BM;
    if (mcount && m0 >= mcount[0]) return;   // dead tile: rows unused downstream

    extern __shared__ char smem[];
    uint32_t sm = smem_u32(smem);
    int tid = threadIdx.x;
    int wid = tid >> 5, lane = tid & 31;
    int wm = wid % TM;
    int wn = wid / TM;
    int n0 = blockIdx.x * BN;

    const char* gAh = (const char*)(Ah + (size_t)m0 * D);
    const char* gBh = (const char*)(Bh + (size_t)n0 * D);

    auto issue = [&](uint32_t st, int kc) {
#pragma unroll
        for (int j = 0; j < OPS; j++) {
            int i = tid + j * THREADS;
            int g = i >> 2;
            int c16 = i & 3;
            const char* src = (g < BM) ? gAh + (size_t)g * (D * 2)
                                       : gBh + (size_t)(g - BM) * (D * 2);
            cp16(st + g * ROWB + c16 * 16, src + kc * 64 + c16 * 16);
        }
        cp_commit();
    };

    float acc[MT][NT][4];
#pragma unroll
    for (int mt = 0; mt < MT; mt++)
#pragma unroll
        for (int nt = 0; nt < NT; nt++)
#pragma unroll
            for (int r = 0; r < 4; r++) acc[mt][nt][r] = 0.0f;

    const int NCH = D / 32;               // 16
    issue(sm, 0);

    int a_row = wm * WM + (lane & 15);
    int a_kb = (lane >> 4) * 16;
    int b_row = wn * WN + ((lane >> 4) & 1) * 8 + (lane & 7);
    int b_kb = ((lane >> 3) & 1) * 16;

    for (int c = 0; c < NCH; c++) {
        uint32_t st = sm + (c & 1) * STAGE;
        if (c + 1 < NCH) {
            issue(sm + ((c + 1) & 1) * STAGE, c + 1);
            cp_wait<1>();
        } else {
            cp_wait<0>();
        }
        __syncthreads();

        uint32_t sAh = st;
        uint32_t sBh = st + BM * ROWB;

#pragma unroll
        for (int kk = 0; kk < 2; kk++) {
            uint32_t ah[MT][4];
#pragma unroll
            for (int mt = 0; mt < MT; mt++)
                ldm_x4(ah[mt], sAh + (a_row + mt * 16) * ROWB + kk * 32 + a_kb);
#pragma unroll
            for (int ng = 0; ng < NG; ng++) {
                uint32_t bh[4];
                ldm_x4(bh, sBh + (b_row + ng * 16) * ROWB + kk * 32 + b_kb);
#pragma unroll
                for (int mt = 0; mt < MT; mt++) {
#pragma unroll
                    for (int hf = 0; hf < 2; hf++)
                        mma_f16(acc[mt][ng * 2 + hf], ah[mt], &bh[hf * 2]);
                }
            }
        }
        __syncthreads();
    }

    // epilogue
#pragma unroll
    for (int mt = 0; mt < MT; mt++) {
        int row0 = m0 + wm * WM + mt * 16 + (lane >> 2);
#pragma unroll
        for (int nt = 0; nt < NT; nt++) {
            int col = n0 + wn * WN + nt * 8 + (lane & 3) * 2;
            float b0 = bias[col], b1 = bias[col + 1];
            float2 v0, v1;
            v0.x = acc[mt][nt][0] + b0; v0.y = acc[mt][nt][1] + b1;
            v1.x = acc[mt][nt][2] + b0; v1.y = acc[mt][nt][3] + b1;
            if (relu) {
                v0.x = fmaxf(v0.x, 0.f); v0.y = fmaxf(v0.y, 0.f);
                v1.x = fmaxf(v1.x, 0.f); v1.y = fmaxf(v1.y, 0.f);
            }
            if (HOUT) {
                __half* Ch = (__half*)Cv;
                __half2 o0 = __floats2half2_rn(v0.x, v0.y);
                __half2 o1 = __floats2half2_rn(v1.x, v1.y);
                *(__half2*)&Ch[(size_t)row0 * ldc + col] = o0;
                *(__half2*)&Ch[(size_t)(row0 + 8) * ldc + col] = o1;
            } else {
                float* C = (float*)Cv;
                *(float2*)&C[(size_t)row0 * ldc + col] = v0;
                *(float2*)&C[(size_t)(row0 + 8) * ldc + col] = v1;
            }
        }
    }
}

// L1: 128x256 tile, 512 threads, fp16 out.  smem = 2*(128+256)*80 = 61440
// L2: 64x128 tile, 256 threads, fp32 out.   smem = 2*(64+128)*80 = 30720
#define SMEM_L1 (2 * (128 + 256) * ROWB)
#define SMEM_L2 (2 * (64 + 128) * ROWB)

// ---------------- launch (single stream) ----------------
extern "C" void kernel_launch(void* const* d_in, const int* in_sizes, int n_in,
                              void* d_out, int out_size) {
    const float* feats = (const float*)d_in[0];
    const float* W1    = (const float*)d_in[1];
    const float* b1    = (const float*)d_in[2];
    const float* W2    = (const float*)d_in[3];
    const float* b2    = (const float*)d_in[4];
    const int*   es1   = (const int*)d_in[5];
    const int*   ed1   = (const int*)d_in[6];
    const int*   es2   = (const int*)d_in[7];
    const int*   ed2   = (const int*)d_in[8];
    float* out = (float*)d_out;

    __half *h1h, *a1h, *a2h, *w1hi, *w2hi;
    int *cnt, *cur, *off1, *srt1, *off2, *srt2, *remap, *ulist, *ucnt;
    cudaGetSymbolAddress((void**)&h1h,   g_h1h);
    cudaGetSymbolAddress((void**)&a1h,   g_a1h);
    cudaGetSymbolAddress((void**)&a2h,   g_a2h);
    cudaGetSymbolAddress((void**)&w1hi,  g_w1hi);
    cudaGetSymbolAddress((void**)&w2hi,  g_w2hi);
    cudaGetSymbolAddress((void**)&cnt,   g_cnt);
    cudaGetSymbolAddress((void**)&cur,   g_cur);
    cudaGetSymbolAddress((void**)&off1,  g_off1);
    cudaGetSymbolAddress((void**)&srt1,  g_srt1);
    cudaGetSymbolAddress((void**)&off2,  g_off2);
    cudaGetSymbolAddress((void**)&srt2,  g_srt2);
    cudaGetSymbolAddress((void**)&remap, g_remap);
    cudaGetSymbolAddress((void**)&ulist, g_ulist);
    cudaGetSymbolAddress((void**)&ucnt,  g_ucnt);

    cudaFuncSetAttribute((void*)gemm_hmma_k<128, 256, 4, 4, true>,
                         cudaFuncAttributeMaxDynamicSharedMemorySize, SMEM_L1);
    cudaFuncSetAttribute((void*)gemm_hmma_k<64, 128, 2, 4, false>,
                         cudaFuncAttributeMaxDynamicSharedMemorySize, SMEM_L2);

    // ---- fused prep: (hist + used + W conv) -> scan(+re-zero, +ulist) -> scatter ----
    prep_k<<<(PREP_N + 255) / 256, 256>>>(ed1, ed2, es2, cnt, W1, w1hi, W2, w2hi);
    scan_all_k<<<3, 1024>>>(cnt, cur, off1, off2, remap, ucnt, ulist);
    scatter_all_k<<<(E1 + E2 + 255) / 256, 256>>>(
        es1, ed1, es2, ed2, cur, remap, srt1, srt2);

    // ---- layer 1 (only used rows, compact) ----
    agg1_k<<<N1_DST, 128>>>(feats, off1, srt1, ulist, ucnt, a1h);
    {
        dim3 grid(D / 256, N1_DST / 128);   // (2, 352); dead M-tiles exit early
        gemm_hmma_k<128, 256, 4, 4, true><<<grid, 512, SMEM_L1>>>(
            a1h, w1hi, b1, h1h, D, 1, ucnt);
    }

    // ---- layer 2 ----
    agg2_k<<<N2_DST, 128>>>(h1h, off2, srt2, remap, a2h);
    {
        dim3 grid(DOUT / 128, N2_DST / 64);  // (2, 64)
        gemm_hmma_k<64, 128, 2, 4, false><<<grid, 256, SMEM_L2>>>(
            a2h, w2hi, b2, out, DOUT, 0, nullptr);
    }
}

// round 15
// speedup vs baseline: 1.0405x; 1.0405x over previous
#include <cuda_runtime.h>
#include <cuda_fp16.h>
#include <cstdint>

// Problem constants
#define N1_SRC 495616
#define N1_DST 45056
#define E1     450560
#define N2_SRC 45056
#define N2_DST 4096
#define E2     40960
#define D      512
#define DOUT   256

// ---------------- device scratch ----------------
__device__ __half g_h1h[(size_t)N1_DST * D];          // layer-1 output (fp16, compact)
__device__ __half g_a1h[(size_t)N1_DST * D];          // layer-1 A (fp16, compact)
__device__ __half g_a2h[(size_t)N2_DST * D];          // layer-2 A (single fp16)
__device__ __half g_w1hi[(size_t)D * D];              // W1^T [N=512,K=512] fp16
__device__ __half g_w2hi[(size_t)DOUT * D];           // W2^T [N=256,K=512] fp16

// cnt1 | cnt2 | used  (one memset)
__device__ int g_cnt[N1_DST + N2_DST + N1_DST];
__device__ int g_cur[N1_DST + N2_DST];
__device__ int g_off1[N1_DST + 1];
__device__ int g_srt1[E1];
__device__ int g_off2[N2_DST + 1];
__device__ int g_srt2[E2];                             // stores REMAPPED src ids
__device__ int g_remap[N1_DST + 1];
__device__ int g_ulist[N1_DST];
__device__ int g_ucnt[1];

// ---------------- PTX helpers (base-target safe) ----------------
__device__ __forceinline__ uint32_t smem_u32(const void* p) {
    uint32_t a;
    asm("{ .reg .u64 t; cvta.to.shared.u64 t, %1; cvt.u32.u64 %0, t; }" : "=r"(a) : "l"(p));
    return a;
}
__device__ __forceinline__ void cp16(uint32_t s, const void* g) {
    asm volatile("cp.async.cg.shared.global [%0], [%1], 16;" :: "r"(s), "l"(g));
}
__device__ __forceinline__ void cp_commit() {
    asm volatile("cp.async.commit_group;" ::: "memory");
}
template <int N>
__device__ __forceinline__ void cp_wait() {
    asm volatile("cp.async.wait_group %0;" :: "n"(N) : "memory");
}
__device__ __forceinline__ void ldm_x4(uint32_t* r, uint32_t addr) {
    asm volatile("ldmatrix.sync.aligned.m8n8.x4.shared.b16 {%0,%1,%2,%3}, [%4];"
                 : "=r"(r[0]), "=r"(r[1]), "=r"(r[2]), "=r"(r[3]) : "r"(addr));
}
// D += A(f16) * B(f16), m16n8k16, fp32 accum
__device__ __forceinline__ void mma_f16(float* c, const uint32_t* a, const uint32_t* b) {
    asm volatile(
        "mma.sync.aligned.m16n8k16.row.col.f32.f16.f16.f32 "
        "{%0,%1,%2,%3}, {%4,%5,%6,%7}, {%8,%9}, {%0,%1,%2,%3};"
        : "+f"(c[0]), "+f"(c[1]), "+f"(c[2]), "+f"(c[3])
        : "r"(a[0]), "r"(a[1]), "r"(a[2]), "r"(a[3]), "r"(b[0]), "r"(b[1]));
}

// ---------------- fused prep: hist + used-marks + weight conversion ----------------
#define PREP_N (E1 + E2 + N2_DST + D * D + DOUT * D)

__global__ void prep_k(const int* __restrict__ ed1, const int* __restrict__ ed2,
                       const int* __restrict__ es2, int* __restrict__ cnt,
                       const float* __restrict__ W1, __half* __restrict__ t1,
                       const float* __restrict__ W2, __half* __restrict__ t2) {
    int* used = cnt + (N1_DST + N2_DST);
    int i = blockIdx.x * blockDim.x + threadIdx.x;
    if (i < E1) {
        atomicAdd(&cnt[ed1[i]], 1);
    } else if (i < E1 + E2) {
        int j = i - E1;
        atomicAdd(&cnt[N1_DST + ed2[j]], 1);
        used[es2[j]] = 1;                 // benign race, deterministic
    } else if (i < E1 + E2 + N2_DST) {
        used[i - E1 - E2] = 1;            // self rows 0..4095
    } else {
        int j = i - (E1 + E2 + N2_DST);
        if (j < D * D) {
            int n = j / D, k = j - n * D;
            t1[j] = __float2half_rn(W1[(size_t)k * D + n]);
        } else if (j < D * D + DOUT * D) {
            j -= D * D;
            int n = j / D, k = j - n * D;
            t2[j] = __float2half_rn(W2[(size_t)k * DOUT + n]);
        }
    }
}

// block 0: cnt1->off1/cur ; block 1: cnt2->off2/cur+N1 ; block 2: used->remap,+ucnt
// 4 elements per thread (n is a multiple of 4096 for all three blocks)
__global__ void scan_all_k(const int* __restrict__ cnt, int* __restrict__ cur,
                           int* __restrict__ off1, int* __restrict__ off2,
                           int* __restrict__ remap, int* __restrict__ ucnt) {
    const int* c; int* cu; int* off; int n;
    if (blockIdx.x == 0)      { c = cnt;                    cu = cur;           off = off1;  n = N1_DST; }
    else if (blockIdx.x == 1) { c = cnt + N1_DST;           cu = cur + N1_DST;  off = off2;  n = N2_DST; }
    else                      { c = cnt + N1_DST + N2_DST;  cu = nullptr;       off = remap; n = N1_DST; }

    __shared__ int wsum[32];
    __shared__ int carry_s;
    int tid = threadIdx.x, lane = tid & 31, w = tid >> 5;
    if (tid == 0) carry_s = 0;
    __syncthreads();
    for (int base = 0; base < n; base += 4096) {
        int i = base + tid * 4;
        int4 v = *(const int4*)&c[i];
        int s = v.x + v.y + v.z + v.w;
        int x = s;
#pragma unroll
        for (int st = 1; st < 32; st <<= 1) {
            int t = __shfl_up_sync(0xFFFFFFFFu, x, st);
            if (lane >= st) x += t;
        }
        if (lane == 31) wsum[w] = x;
        __syncthreads();
        if (w == 0) {
            int y = wsum[lane];
#pragma unroll
            for (int st = 1; st < 32; st <<= 1) {
                int t = __shfl_up_sync(0xFFFFFFFFu, y, st);
                if (lane >= st) y += t;
            }
            wsum[lane] = y;
        }
        __syncthreads();
        int excl = carry_s + (w ? wsum[w - 1] : 0) + x - s;   // exclusive prefix of item 0
        int4 o;
        o.x = excl;
        o.y = excl + v.x;
        o.z = excl + v.x + v.y;
        o.w = excl + v.x + v.y + v.z;
        *(int4*)&off[i] = o;
        if (cu) *(int4*)&cu[i] = o;
        __syncthreads();
        if (tid == 1023) carry_s = excl + s;
        __syncthreads();
    }
    if (threadIdx.x == 0) {
        off[n] = carry_s;
        if (blockIdx.x == 2) ucnt[0] = carry_s;
    }
}

// scatter both edge lists (layer-2 sources remapped) + build used_list
__global__ void scatter_all_k(const int* __restrict__ es1, const int* __restrict__ ed1,
                              const int* __restrict__ es2, const int* __restrict__ ed2,
                              int* __restrict__ cur, const int* __restrict__ cnt,
                              const int* __restrict__ remap,
                              int* __restrict__ srt1, int* __restrict__ srt2,
                              int* __restrict__ ulist) {
    const int* used = cnt + (N1_DST + N2_DST);
    int i = blockIdx.x * blockDim.x + threadIdx.x;
    if (i < E1) {
        int p = atomicAdd(&cur[ed1[i]], 1);
        srt1[p] = es1[i];
    } else if (i < E1 + E2) {
        int j = i - E1;
        int p = atomicAdd(&cur[N1_DST + ed2[j]], 1);
        srt2[p] = remap[es2[j]];          // remapped into compact h1 space
    } else if (i < E1 + E2 + N1_DST) {
        int k = i - E1 - E2;
        if (used[k]) ulist[remap[k]] = k;
    }
}

// ---------------- layer-1 aggregation: only USED nodes, compact fp16 out ----------------
__global__ void __launch_bounds__(128)
agg1_k(const float* __restrict__ feat, const int* __restrict__ off,
       const int* __restrict__ srt, const int* __restrict__ ulist,
       const int* __restrict__ ucnt, __half* __restrict__ ahi) {
    int b = blockIdx.x;
    if (b >= ucnt[0]) return;
    int node = ulist[b];
    int t = threadIdx.x;                  // covers cols t*4 .. t*4+3
    const float4* fp = (const float4*)feat;
    int bg = off[node], e = off[node + 1];

    float4 acc = fp[(size_t)node * (D / 4) + t];
    int j = bg;
    for (; j + 3 < e; j += 4) {
        int s0 = srt[j], s1 = srt[j + 1], s2 = srt[j + 2], s3 = srt[j + 3];
        float4 v0 = fp[(size_t)s0 * (D / 4) + t];
        float4 v1 = fp[(size_t)s1 * (D / 4) + t];
        float4 v2 = fp[(size_t)s2 * (D / 4) + t];
        float4 v3 = fp[(size_t)s3 * (D / 4) + t];
        acc.x += v0.x + v1.x + v2.x + v3.x;
        acc.y += v0.y + v1.y + v2.y + v3.y;
        acc.z += v0.z + v1.z + v2.z + v3.z;
        acc.w += v0.w + v1.w + v2.w + v3.w;
    }
    for (; j < e; j++) {
        int s0 = srt[j];
        float4 v0 = fp[(size_t)s0 * (D / 4) + t];
        acc.x += v0.x; acc.y += v0.y; acc.z += v0.z; acc.w += v0.w;
    }
    float sc = 1.0f / (float)(e - bg + 1);
    __half2 p01 = __floats2half2_rn(acc.x * sc, acc.y * sc);
    __half2 p23 = __floats2half2_rn(acc.z * sc, acc.w * sc);
    uint2 o;
    o.x = *(uint32_t*)&p01;
    o.y = *(uint32_t*)&p23;
    ((uint2*)ahi)[(size_t)b * (D / 4) + t] = o;       // compact row b
}

// ---------------- layer-2 aggregation: fp16 gather (compact h1) -> single fp16 ----------------
__global__ void __launch_bounds__(128)
agg2_k(const __half* __restrict__ feat, const int* __restrict__ off,
       const int* __restrict__ srt, const int* __restrict__ remap,
       __half* __restrict__ ah) {
    int node = blockIdx.x;
    int t = threadIdx.x;                  // covers cols t*4 .. t*4+3
    const uint2* fp = (const uint2*)feat;
    int b = off[node], e = off[node + 1];

    uint2 sv = fp[(size_t)remap[node] * (D / 4) + t];   // self row (remapped)
    float2 f01 = __half22float2(*(__half2*)&sv.x);
    float2 f23 = __half22float2(*(__half2*)&sv.y);
    float a0 = f01.x, a1 = f01.y, a2 = f23.x, a3 = f23.y;

    int j = b;
    for (; j + 1 < e; j += 2) {
        uint2 v0 = fp[(size_t)srt[j] * (D / 4) + t];
        uint2 v1 = fp[(size_t)srt[j + 1] * (D / 4) + t];
        float2 u0 = __half22float2(*(__half2*)&v0.x);
        float2 u1 = __half22float2(*(__half2*)&v0.y);
        float2 w0 = __half22float2(*(__half2*)&v1.x);
        float2 w1 = __half22float2(*(__half2*)&v1.y);
        a0 += u0.x + w0.x; a1 += u0.y + w0.y;
        a2 += u1.x + w1.x; a3 += u1.y + w1.y;
    }
    if (j < e) {
        uint2 v0 = fp[(size_t)srt[j] * (D / 4) + t];
        float2 u0 = __half22float2(*(__half2*)&v0.x);
        float2 u1 = __half22float2(*(__half2*)&v0.y);
        a0 += u0.x; a1 += u0.y; a2 += u1.x; a3 += u1.y;
    }
    float sc = 1.0f / (float)(e - b + 1);
    __half2 p01 = __floats2half2_rn(a0 * sc, a1 * sc);
    __half2 p23 = __floats2half2_rn(a2 * sc, a3 * sc);
    uint2 o;
    o.x = *(uint32_t*)&p01;
    o.y = *(uint32_t*)&p23;
    ((uint2*)ah)[(size_t)node * (D / 4) + t] = o;
}

// ---------------- HMMA fp16 GEMM (templated) ----------------
// C = Ah*Bh + bias, opt relu. HOUT: fp16 out. mcount: optional M early-exit bound.
#define ROWB 80

template <int BM, int BN, int TM, int TN, bool HOUT>
__global__ void __launch_bounds__(TM * TN * 32, 1)
gemm_hmma_k(const __half* __restrict__ Ah, const __half* __restrict__ Bh,
            const float* __restrict__ bias, void* __restrict__ Cv,
            int ldc, int relu, const int* __restrict__ mcount) {
    constexpr int THREADS = TM * TN * 32;
    constexpr int WM = BM / TM;
    constexpr int WN = BN / TN;
    constexpr int MT = WM / 16;
    constexpr int NG = WN / 16;
    constexpr int NT = WN / 8;
    constexpr int TOTROWS = BM + BN;
    constexpr int STAGE = TOTROWS * ROWB;
    constexpr int OPS = TOTROWS * 4 / THREADS;

    int m0 = blockIdx.y * BM;
    if (mcount && m0 >= mcount[0]) return;   // dead tile: rows unused downstream

    extern __shared__ char smem[];
    uint32_t sm = smem_u32(smem);
    int tid = threadIdx.x;
    int wid = tid >> 5, lane = tid & 31;
    int wm = wid % TM;
    int wn = wid / TM;
    int n0 = blockIdx.x * BN;

    const char* gAh = (const char*)(Ah + (size_t)m0 * D);
    const char* gBh = (const char*)(Bh + (size_t)n0 * D);

    auto issue = [&](uint32_t st, int kc) {
#pragma unroll
        for (int j = 0; j < OPS; j++) {
            int i = tid + j * THREADS;
            int g = i >> 2;
            int c16 = i & 3;
            const char* src = (g < BM) ? gAh + (size_t)g * (D * 2)
                                       : gBh + (size_t)(g - BM) * (D * 2);
            cp16(st + g * ROWB + c16 * 16, src + kc * 64 + c16 * 16);
        }
        cp_commit();
    };

    float acc[MT][NT][4];
#pragma unroll
    for (int mt = 0; mt < MT; mt++)
#pragma unroll
        for (int nt = 0; nt < NT; nt++)
#pragma unroll
            for (int r = 0; r < 4; r++) acc[mt][nt][r] = 0.0f;

    const int NCH = D / 32;               // 16
    issue(sm, 0);

    int a_row = wm * WM + (lane & 15);
    int a_kb = (lane >> 4) * 16;
    int b_row = wn * WN + ((lane >> 4) & 1) * 8 + (lane & 7);
    int b_kb = ((lane >> 3) & 1) * 16;

    for (int c = 0; c < NCH; c++) {
        uint32_t st = sm + (c & 1) * STAGE;
        if (c + 1 < NCH) {
            issue(sm + ((c + 1) & 1) * STAGE, c + 1);
            cp_wait<1>();
        } else {
            cp_wait<0>();
        }
        __syncthreads();

        uint32_t sAh = st;
        uint32_t sBh = st + BM * ROWB;

#pragma unroll
        for (int kk = 0; kk < 2; kk++) {
            uint32_t ah[MT][4];
#pragma unroll
            for (int mt = 0; mt < MT; mt++)
                ldm_x4(ah[mt], sAh + (a_row + mt * 16) * ROWB + kk * 32 + a_kb);
#pragma unroll
            for (int ng = 0; ng < NG; ng++) {
                uint32_t bh[4];
                ldm_x4(bh, sBh + (b_row + ng * 16) * ROWB + kk * 32 + b_kb);
#pragma unroll
                for (int mt = 0; mt < MT; mt++) {
#pragma unroll
                    for (int hf = 0; hf < 2; hf++)
                        mma_f16(acc[mt][ng * 2 + hf], ah[mt], &bh[hf * 2]);
                }
            }
        }
        __syncthreads();
    }

    // epilogue
#pragma unroll
    for (int mt = 0; mt < MT; mt++) {
        int row0 = m0 + wm * WM + mt * 16 + (lane >> 2);
#pragma unroll
        for (int nt = 0; nt < NT; nt++) {
            int col = n0 + wn * WN + nt * 8 + (lane & 3) * 2;
            float b0 = bias[col], b1 = bias[col + 1];
            float2 v0, v1;
            v0.x = acc[mt][nt][0] + b0; v0.y = acc[mt][nt][1] + b1;
            v1.x = acc[mt][nt][2] + b0; v1.y = acc[mt][nt][3] + b1;
            if (relu) {
                v0.x = fmaxf(v0.x, 0.f); v0.y = fmaxf(v0.y, 0.f);
                v1.x = fmaxf(v1.x, 0.f); v1.y = fmaxf(v1.y, 0.f);
            }
            if (HOUT) {
                __half* Ch = (__half*)Cv;
                __half2 o0 = __floats2half2_rn(v0.x, v0.y);
                __half2 o1 = __floats2half2_rn(v1.x, v1.y);
                *(__half2*)&Ch[(size_t)row0 * ldc + col] = o0;
                *(__half2*)&Ch[(size_t)(row0 + 8) * ldc + col] = o1;
            } else {
                float* C = (float*)Cv;
                *(float2*)&C[(size_t)row0 * ldc + col] = v0;
                *(float2*)&C[(size_t)(row0 + 8) * ldc + col] = v1;
            }
        }
    }
}

// L1: 128x256 tile, 512 threads, fp16 out.  smem = 2*(128+256)*80 = 61440
// L2: 64x128 tile, 256 threads, fp32 out.   smem = 2*(64+128)*80 = 30720
#define SMEM_L1 (2 * (128 + 256) * ROWB)
#define SMEM_L2 (2 * (64 + 128) * ROWB)

// ---------------- launch (single stream) ----------------
extern "C" void kernel_launch(void* const* d_in, const int* in_sizes, int n_in,
                              void* d_out, int out_size) {
    const float* feats = (const float*)d_in[0];
    const float* W1    = (const float*)d_in[1];
    const float* b1    = (const float*)d_in[2];
    const float* W2    = (const float*)d_in[3];
    const float* b2    = (const float*)d_in[4];
    const int*   es1   = (const int*)d_in[5];
    const int*   ed1   = (const int*)d_in[6];
    const int*   es2   = (const int*)d_in[7];
    const int*   ed2   = (const int*)d_in[8];
    float* out = (float*)d_out;

    __half *h1h, *a1h, *a2h, *w1hi, *w2hi;
    int *cnt, *cur, *off1, *srt1, *off2, *srt2, *remap, *ulist, *ucnt;
    cudaGetSymbolAddress((void**)&h1h,   g_h1h);
    cudaGetSymbolAddress((void**)&a1h,   g_a1h);
    cudaGetSymbolAddress((void**)&a2h,   g_a2h);
    cudaGetSymbolAddress((void**)&w1hi,  g_w1hi);
    cudaGetSymbolAddress((void**)&w2hi,  g_w2hi);
    cudaGetSymbolAddress((void**)&cnt,   g_cnt);
    cudaGetSymbolAddress((void**)&cur,   g_cur);
    cudaGetSymbolAddress((void**)&off1,  g_off1);
    cudaGetSymbolAddress((void**)&srt1,  g_srt1);
    cudaGetSymbolAddress((void**)&off2,  g_off2);
    cudaGetSymbolAddress((void**)&srt2,  g_srt2);
    cudaGetSymbolAddress((void**)&remap, g_remap);
    cudaGetSymbolAddress((void**)&ulist, g_ulist);
    cudaGetSymbolAddress((void**)&ucnt,  g_ucnt);

    cudaFuncSetAttribute((void*)gemm_hmma_k<128, 256, 4, 4, true>,
                         cudaFuncAttributeMaxDynamicSharedMemorySize, SMEM_L1);
    cudaFuncSetAttribute((void*)gemm_hmma_k<64, 128, 2, 4, false>,
                         cudaFuncAttributeMaxDynamicSharedMemorySize, SMEM_L2);

    // ---- fused prep: memset -> (hist + used-marks + weight conversion) -> scan -> scatter ----
    cudaMemsetAsync(cnt, 0, (2 * N1_DST + N2_DST) * sizeof(int));
    prep_k<<<(PREP_N + 255) / 256, 256>>>(ed1, ed2, es2, cnt, W1, w1hi, W2, w2hi);
    scan_all_k<<<3, 1024>>>(cnt, cur, off1, off2, remap, ucnt);
    scatter_all_k<<<(E1 + E2 + N1_DST + 255) / 256, 256>>>(
        es1, ed1, es2, ed2, cur, cnt, remap, srt1, srt2, ulist);

    // ---- layer 1 (only used rows, compact) ----
    agg1_k<<<N1_DST, 128>>>(feats, off1, srt1, ulist, ucnt, a1h);
    {
        dim3 grid(D / 256, N1_DST / 128);   // (2, 352); dead M-tiles exit early
        gemm_hmma_k<128, 256, 4, 4, true><<<grid, 512, SMEM_L1>>>(
            a1h, w1hi, b1, h1h, D, 1, ucnt);
    }

    // ---- layer 2 ----
    agg2_k<<<N2_DST, 128>>>(h1h, off2, srt2, remap, a2h);
    {
        dim3 grid(DOUT / 128, N2_DST / 64);  // (2, 64)
        gemm_hmma_k<64, 128, 2, 4, false><<<grid, 256, SMEM_L2>>>(
            a2h, w2hi, b2, out, DOUT, 0, nullptr);
    }
}

// round 16
// speedup vs baseline: 1.1121x; 1.0688x over previous
#include <cuda_runtime.h>
#include <cuda_fp16.h>
#include <cstdint>

// Problem constants
#define N1_SRC 495616
#define N1_DST 45056
#define E1     450560
#define N2_SRC 45056
#define N2_DST 4096
#define E2     40960
#define D      512
#define DOUT   256

// ---------------- device scratch ----------------
__device__ __half g_h1h[(size_t)N1_DST * D];          // layer-1 output (fp16, compact)
__device__ __half g_a1h[(size_t)N1_DST * D];          // layer-1 A (fp16, compact)
__device__ __half g_a2h[(size_t)N2_DST * D];          // layer-2 A (single fp16)
__device__ __half g_w1hi[(size_t)D * D];              // W1^T [N=512,K=512] fp16
__device__ __half g_w2hi[(size_t)DOUT * D];           // W2^T [N=256,K=512] fp16

// cnt1 | cnt2 | used  (one memset)
__device__ int g_cnt[N1_DST + N2_DST + N1_DST];
__device__ int g_cur[N1_DST + N2_DST];
__device__ int g_off1[N1_DST + 1];
__device__ int g_srt1[E1];
__device__ int g_off2[N2_DST + 1];
__device__ int g_srt2[E2];                             // stores REMAPPED src ids
__device__ int g_remap[N1_DST + 1];
__device__ int g_ulist[N1_DST];
__device__ int g_ucnt[1];

// ---------------- PTX helpers (base-target safe) ----------------
__device__ __forceinline__ uint32_t smem_u32(const void* p) {
    uint32_t a;
    asm("{ .reg .u64 t; cvta.to.shared.u64 t, %1; cvt.u32.u64 %0, t; }" : "=r"(a) : "l"(p));
    return a;
}
__device__ __forceinline__ void cp16(uint32_t s, const void* g) {
    asm volatile("cp.async.cg.shared.global [%0], [%1], 16;" :: "r"(s), "l"(g));
}
__device__ __forceinline__ void cp_commit() {
    asm volatile("cp.async.commit_group;" ::: "memory");
}
template <int N>
__device__ __forceinline__ void cp_wait() {
    asm volatile("cp.async.wait_group %0;" :: "n"(N) : "memory");
}
__device__ __forceinline__ void ldm_x4(uint32_t* r, uint32_t addr) {
    asm volatile("ldmatrix.sync.aligned.m8n8.x4.shared.b16 {%0,%1,%2,%3}, [%4];"
                 : "=r"(r[0]), "=r"(r[1]), "=r"(r[2]), "=r"(r[3]) : "r"(addr));
}
// D += A(f16) * B(f16), m16n8k16, fp32 accum
__device__ __forceinline__ void mma_f16(float* c, const uint32_t* a, const uint32_t* b) {
    asm volatile(
        "mma.sync.aligned.m16n8k16.row.col.f32.f16.f16.f32 "
        "{%0,%1,%2,%3}, {%4,%5,%6,%7}, {%8,%9}, {%0,%1,%2,%3};"
        : "+f"(c[0]), "+f"(c[1]), "+f"(c[2]), "+f"(c[3])
        : "r"(a[0]), "r"(a[1]), "r"(a[2]), "r"(a[3]), "r"(b[0]), "r"(b[1]));
}

// ---------------- fused prep: hist + used-marks + weight conversion ----------------
#define PREP_N (E1 + E2 + N2_DST + D * D + DOUT * D)

__global__ void prep_k(const int* __restrict__ ed1, const int* __restrict__ ed2,
                       const int* __restrict__ es2, int* __restrict__ cnt,
                       const float* __restrict__ W1, __half* __restrict__ t1,
                       const float* __restrict__ W2, __half* __restrict__ t2) {
    int* used = cnt + (N1_DST + N2_DST);
    int i = blockIdx.x * blockDim.x + threadIdx.x;
    if (i < E1) {
        atomicAdd(&cnt[ed1[i]], 1);
    } else if (i < E1 + E2) {
        int j = i - E1;
        atomicAdd(&cnt[N1_DST + ed2[j]], 1);
        used[es2[j]] = 1;                 // benign race, deterministic
    } else if (i < E1 + E2 + N2_DST) {
        used[i - E1 - E2] = 1;            // self rows 0..4095
    } else {
        int j = i - (E1 + E2 + N2_DST);
        if (j < D * D) {
            int n = j / D, k = j - n * D;
            t1[j] = __float2half_rn(W1[(size_t)k * D + n]);
        } else if (j < D * D + DOUT * D) {
            j -= D * D;
            int n = j / D, k = j - n * D;
            t2[j] = __float2half_rn(W2[(size_t)k * DOUT + n]);
        }
    }
}

// block 0: cnt1->off1/cur ; block 1: cnt2->off2/cur+N1 ; block 2: used->remap,+ucnt
__global__ void scan_all_k(const int* __restrict__ cnt, int* __restrict__ cur,
                           int* __restrict__ off1, int* __restrict__ off2,
                           int* __restrict__ remap, int* __restrict__ ucnt) {
    const int* c; int* cu; int* off; int n;
    if (blockIdx.x == 0)      { c = cnt;                    cu = cur;           off = off1;  n = N1_DST; }
    else if (blockIdx.x == 1) { c = cnt + N1_DST;           cu = cur + N1_DST;  off = off2;  n = N2_DST; }
    else                      { c = cnt + N1_DST + N2_DST;  cu = nullptr;       off = remap; n = N1_DST; }

    __shared__ int wsum[32];
    __shared__ int carry_s;
    int tid = threadIdx.x, lane = tid & 31, w = tid >> 5;
    if (tid == 0) carry_s = 0;
    __syncthreads();
    for (int base = 0; base < n; base += 4096) {
        int i = base + tid * 4;
        int4 v = *(const int4*)&c[i];
        int s = v.x + v.y + v.z + v.w;
        int x = s;
#pragma unroll
        for (int st = 1; st < 32; st <<= 1) {
            int t = __shfl_up_sync(0xFFFFFFFFu, x, st);
            if (lane >= st) x += t;
        }
        if (lane == 31) wsum[w] = x;
        __syncthreads();
        if (w == 0) {
            int y = wsum[lane];
#pragma unroll
            for (int st = 1; st < 32; st <<= 1) {
                int t = __shfl_up_sync(0xFFFFFFFFu, y, st);
                if (lane >= st) y += t;
            }
            wsum[lane] = y;
        }
        __syncthreads();
        int excl = carry_s + (w ? wsum[w - 1] : 0) + x - s;   // exclusive prefix of item 0
        int4 o;
        o.x = excl;
        o.y = excl + v.x;
        o.z = excl + v.x + v.y;
        o.w = excl + v.x + v.y + v.z;
        *(int4*)&off[i] = o;
        if (cu) *(int4*)&cu[i] = o;
        __syncthreads();
        if (tid == 1023) carry_s = excl + s;
        __syncthreads();
    }
    if (threadIdx.x == 0) {
        off[n] = carry_s;
        if (blockIdx.x == 2) ucnt[0] = carry_s;
    }
}

// scatter both edge lists (layer-2 sources remapped) + build used_list
__global__ void scatter_all_k(const int* __restrict__ es1, const int* __restrict__ ed1,
                              const int* __restrict__ es2, const int* __restrict__ ed2,
                              int* __restrict__ cur, const int* __restrict__ cnt,
                              const int* __restrict__ remap,
                              int* __restrict__ srt1, int* __restrict__ srt2,
                              int* __restrict__ ulist) {
    const int* used = cnt + (N1_DST + N2_DST);
    int i = blockIdx.x * blockDim.x + threadIdx.x;
    if (i < E1) {
        int p = atomicAdd(&cur[ed1[i]], 1);
        srt1[p] = es1[i];
    } else if (i < E1 + E2) {
        int j = i - E1;
        int p = atomicAdd(&cur[N1_DST + ed2[j]], 1);
        srt2[p] = remap[es2[j]];          // remapped into compact h1 space
    } else if (i < E1 + E2 + N1_DST) {
        int k = i - E1 - E2;
        if (used[k]) ulist[remap[k]] = k;
    }
}

// ---------------- layer-1 aggregation: 2 used nodes per 256-thread CTA ----------------
__global__ void __launch_bounds__(256)
agg1_k(const float* __restrict__ feat, const int* __restrict__ off,
       const int* __restrict__ srt, const int* __restrict__ ulist,
       const int* __restrict__ ucnt, __half* __restrict__ ahi) {
    int b = blockIdx.x * 2 + (threadIdx.x >> 7);
    if (b >= ucnt[0]) return;
    int node = ulist[b];
    int t = threadIdx.x & 127;            // covers cols t*4 .. t*4+3
    const float4* fp = (const float4*)feat;
    int bg = off[node], e = off[node + 1];

    float4 acc = fp[(size_t)node * (D / 4) + t];
    int j = bg;
    for (; j + 3 < e; j += 4) {
        int s0 = srt[j], s1 = srt[j + 1], s2 = srt[j + 2], s3 = srt[j + 3];
        float4 v0 = fp[(size_t)s0 * (D / 4) + t];
        float4 v1 = fp[(size_t)s1 * (D / 4) + t];
        float4 v2 = fp[(size_t)s2 * (D / 4) + t];
        float4 v3 = fp[(size_t)s3 * (D / 4) + t];
        acc.x += v0.x + v1.x + v2.x + v3.x;
        acc.y += v0.y + v1.y + v2.y + v3.y;
        acc.z += v0.z + v1.z + v2.z + v3.z;
        acc.w += v0.w + v1.w + v2.w + v3.w;
    }
    for (; j < e; j++) {
        int s0 = srt[j];
        float4 v0 = fp[(size_t)s0 * (D / 4) + t];
        acc.x += v0.x; acc.y += v0.y; acc.z += v0.z; acc.w += v0.w;
    }
    float sc = 1.0f / (float)(e - bg + 1);
    __half2 p01 = __floats2half2_rn(acc.x * sc, acc.y * sc);
    __half2 p23 = __floats2half2_rn(acc.z * sc, acc.w * sc);
    uint2 o;
    o.x = *(uint32_t*)&p01;
    o.y = *(uint32_t*)&p23;
    ((uint2*)ahi)[(size_t)b * (D / 4) + t] = o;       // compact row b
}

// ---------------- layer-2 aggregation: fp16 gather (compact h1) -> single fp16 ----------------
__global__ void __launch_bounds__(128)
agg2_k(const __half* __restrict__ feat, const int* __restrict__ off,
       const int* __restrict__ srt, const int* __restrict__ remap,
       __half* __restrict__ ah) {
    int node = blockIdx.x;
    int t = threadIdx.x;                  // covers cols t*4 .. t*4+3
    const uint2* fp = (const uint2*)feat;
    int b = off[node], e = off[node + 1];

    uint2 sv = fp[(size_t)remap[node] * (D / 4) + t];   // self row (remapped)
    float2 f01 = __half22float2(*(__half2*)&sv.x);
    float2 f23 = __half22float2(*(__half2*)&sv.y);
    float a0 = f01.x, a1 = f01.y, a2 = f23.x, a3 = f23.y;

    int j = b;
    for (; j + 1 < e; j += 2) {
        uint2 v0 = fp[(size_t)srt[j] * (D / 4) + t];
        uint2 v1 = fp[(size_t)srt[j + 1] * (D / 4) + t];
        float2 u0 = __half22float2(*(__half2*)&v0.x);
        float2 u1 = __half22float2(*(__half2*)&v0.y);
        float2 w0 = __half22float2(*(__half2*)&v1.x);
        float2 w1 = __half22float2(*(__half2*)&v1.y);
        a0 += u0.x + w0.x; a1 += u0.y + w0.y;
        a2 += u1.x + w1.x; a3 += u1.y + w1.y;
    }
    if (j < e) {
        uint2 v0 = fp[(size_t)srt[j] * (D / 4) + t];
        float2 u0 = __half22float2(*(__half2*)&v0.x);
        float2 u1 = __half22float2(*(__half2*)&v0.y);
        a0 += u0.x; a1 += u0.y; a2 += u1.x; a3 += u1.y;
    }
    float sc = 1.0f / (float)(e - b + 1);
    __half2 p01 = __floats2half2_rn(a0 * sc, a1 * sc);
    __half2 p23 = __floats2half2_rn(a2 * sc, a3 * sc);
    uint2 o;
    o.x = *(uint32_t*)&p01;
    o.y = *(uint32_t*)&p23;
    ((uint2*)ah)[(size_t)node * (D / 4) + t] = o;
}

// ---------------- HMMA fp16 GEMM (BK=64, templated) ----------------
// C = Ah*Bh + bias, opt relu. HOUT: fp16 out. mcount: optional M early-exit bound.
// Row = 64 fp16 = 128B data + 16B pad = 144B (4-bank shift/row, conflict-free ldmatrix).
#define ROWB 144

template <int BM, int BN, int TM, int TN, bool HOUT>
__global__ void __launch_bounds__(TM * TN * 32, 1)
gemm_hmma_k(const __half* __restrict__ Ah, const __half* __restrict__ Bh,
            const float* __restrict__ bias, void* __restrict__ Cv,
            int ldc, int relu, const int* __restrict__ mcount) {
    constexpr int THREADS = TM * TN * 32;
    constexpr int WM = BM / TM;
    constexpr int WN = BN / TN;
    constexpr int MT = WM / 16;
    constexpr int NG = WN / 16;
    constexpr int NT = WN / 8;
    constexpr int TOTROWS = BM + BN;
    constexpr int STAGE = TOTROWS * ROWB;
    constexpr int OPS = TOTROWS * 8 / THREADS;   // 8 x 16B per 128B row

    int m0 = blockIdx.y * BM;
    if (mcount && m0 >= mcount[0]) return;   // dead tile: rows unused downstream

    extern __shared__ char smem[];
    uint32_t sm = smem_u32(smem);
    int tid = threadIdx.x;
    int wid = tid >> 5, lane = tid & 31;
    int wm = wid % TM;
    int wn = wid / TM;
    int n0 = blockIdx.x * BN;

    const char* gAh = (const char*)(Ah + (size_t)m0 * D);
    const char* gBh = (const char*)(Bh + (size_t)n0 * D);

    auto issue = [&](uint32_t st, int kc) {
#pragma unroll
        for (int j = 0; j < OPS; j++) {
            int i = tid + j * THREADS;
            int g = i >> 3;
            int c16 = i & 7;
            const char* src = (g < BM) ? gAh + (size_t)g * (D * 2)
                                       : gBh + (size_t)(g - BM) * (D * 2);
            cp16(st + g * ROWB + c16 * 16, src + kc * 128 + c16 * 16);
        }
        cp_commit();
    };

    float acc[MT][NT][4];
#pragma unroll
    for (int mt = 0; mt < MT; mt++)
#pragma unroll
        for (int nt = 0; nt < NT; nt++)
#pragma unroll
            for (int r = 0; r < 4; r++) acc[mt][nt][r] = 0.0f;

    const int NCH = D / 64;               // 8
    issue(sm, 0);

    int a_row = wm * WM + (lane & 15);
    int a_kb = (lane >> 4) * 16;
    int b_row = wn * WN + ((lane >> 4) & 1) * 8 + (lane & 7);
    int b_kb = ((lane >> 3) & 1) * 16;

    for (int c = 0; c < NCH; c++) {
        uint32_t st = sm + (c & 1) * STAGE;
        if (c + 1 < NCH) {
            issue(sm + ((c + 1) & 1) * STAGE, c + 1);
            cp_wait<1>();
        } else {
            cp_wait<0>();
        }
        __syncthreads();

        uint32_t sAh = st;
        uint32_t sBh = st + BM * ROWB;

#pragma unroll
        for (int kk = 0; kk < 4; kk++) {
            uint32_t ah[MT][4];
#pragma unroll
            for (int mt = 0; mt < MT; mt++)
                ldm_x4(ah[mt], sAh + (a_row + mt * 16) * ROWB + kk * 32 + a_kb);
#pragma unroll
            for (int ng = 0; ng < NG; ng++) {
                uint32_t bh[4];
                ldm_x4(bh, sBh + (b_row + ng * 16) * ROWB + kk * 32 + b_kb);
#pragma unroll
                for (int mt = 0; mt < MT; mt++) {
#pragma unroll
                    for (int hf = 0; hf < 2; hf++)
                        mma_f16(acc[mt][ng * 2 + hf], ah[mt], &bh[hf * 2]);
                }
            }
        }
        __syncthreads();
    }

    // epilogue
#pragma unroll
    for (int mt = 0; mt < MT; mt++) {
        int row0 = m0 + wm * WM + mt * 16 + (lane >> 2);
#pragma unroll
        for (int nt = 0; nt < NT; nt++) {
            int col = n0 + wn * WN + nt * 8 + (lane & 3) * 2;
            float b0 = bias[col], b1 = bias[col + 1];
            float2 v0, v1;
            v0.x = acc[mt][nt][0] + b0; v0.y = acc[mt][nt][1] + b1;
            v1.x = acc[mt][nt][2] + b0; v1.y = acc[mt][nt][3] + b1;
            if (relu) {
                v0.x = fmaxf(v0.x, 0.f); v0.y = fmaxf(v0.y, 0.f);
                v1.x = fmaxf(v1.x, 0.f); v1.y = fmaxf(v1.y, 0.f);
            }
            if (HOUT) {
                __half* Ch = (__half*)Cv;
                __half2 o0 = __floats2half2_rn(v0.x, v0.y);
                __half2 o1 = __floats2half2_rn(v1.x, v1.y);
                *(__half2*)&Ch[(size_t)row0 * ldc + col] = o0;
                *(__half2*)&Ch[(size_t)(row0 + 8) * ldc + col] = o1;
            } else {
                float* C = (float*)Cv;
                *(float2*)&C[(size_t)row0 * ldc + col] = v0;
                *(float2*)&C[(size_t)(row0 + 8) * ldc + col] = v1;
            }
        }
    }
}

// L1: 128x256 tile, 512 threads, fp16 out.  smem = 2*(128+256)*144 = 110592
// L2: 64x128 tile, 256 threads, fp32 out.   smem = 2*(64+128)*144 = 55296
#define SMEM_L1 (2 * (128 + 256) * ROWB)
#define SMEM_L2 (2 * (64 + 128) * ROWB)

// ---------------- launch (single stream) ----------------
extern "C" void kernel_launch(void* const* d_in, const int* in_sizes, int n_in,
                              void* d_out, int out_size) {
    const float* feats = (const float*)d_in[0];
    const float* W1    = (const float*)d_in[1];
    const float* b1    = (const float*)d_in[2];
    const float* W2    = (const float*)d_in[3];
    const float* b2    = (const float*)d_in[4];
    const int*   es1   = (const int*)d_in[5];
    const int*   ed1   = (const int*)d_in[6];
    const int*   es2   = (const int*)d_in[7];
    const int*   ed2   = (const int*)d_in[8];
    float* out = (float*)d_out;

    __half *h1h, *a1h, *a2h, *w1hi, *w2hi;
    int *cnt, *cur, *off1, *srt1, *off2, *srt2, *remap, *ulist, *ucnt;
    cudaGetSymbolAddress((void**)&h1h,   g_h1h);
    cudaGetSymbolAddress((void**)&a1h,   g_a1h);
    cudaGetSymbolAddress((void**)&a2h,   g_a2h);
    cudaGetSymbolAddress((void**)&w1hi,  g_w1hi);
    cudaGetSymbolAddress((void**)&w2hi,  g_w2hi);
    cudaGetSymbolAddress((void**)&cnt,   g_cnt);
    cudaGetSymbolAddress((void**)&cur,   g_cur);
    cudaGetSymbolAddress((void**)&off1,  g_off1);
    cudaGetSymbolAddress((void**)&srt1,  g_srt1);
    cudaGetSymbolAddress((void**)&off2,  g_off2);
    cudaGetSymbolAddress((void**)&srt2,  g_srt2);
    cudaGetSymbolAddress((void**)&remap, g_remap);
    cudaGetSymbolAddress((void**)&ulist, g_ulist);
    cudaGetSymbolAddress((void**)&ucnt,  g_ucnt);

    cudaFuncSetAttribute((void*)gemm_hmma_k<128, 256, 4, 4, true>,
                         cudaFuncAttributeMaxDynamicSharedMemorySize, SMEM_L1);
    cudaFuncSetAttribute((void*)gemm_hmma_k<64, 128, 2, 4, false>,
                         cudaFuncAttributeMaxDynamicSharedMemorySize, SMEM_L2);

    // ---- fused prep: memset -> (hist + used-marks + weight conversion) -> scan -> scatter ----
    cudaMemsetAsync(cnt, 0, (2 * N1_DST + N2_DST) * sizeof(int));
    prep_k<<<(PREP_N + 255) / 256, 256>>>(ed1, ed2, es2, cnt, W1, w1hi, W2, w2hi);
    scan_all_k<<<3, 1024>>>(cnt, cur, off1, off2, remap, ucnt);
    scatter_all_k<<<(E1 + E2 + N1_DST + 255) / 256, 256>>>(
        es1, ed1, es2, ed2, cur, cnt, remap, srt1, srt2, ulist);

    // ---- layer 1 (only used rows, compact) ----
    agg1_k<<<N1_DST / 2, 256>>>(feats, off1, srt1, ulist, ucnt, a1h);
    {
        dim3 grid(D / 256, N1_DST / 128);   // (2, 352); dead M-tiles exit early
        gemm_hmma_k<128, 256, 4, 4, true><<<grid, 512, SMEM_L1>>>(
            a1h, w1hi, b1, h1h, D, 1, ucnt);
    }

    // ---- layer 2 ----
    agg2_k<<<N2_DST, 128>>>(h1h, off2, srt2, remap, a2h);
    {
        dim3 grid(DOUT / 128, N2_DST / 64);  // (2, 64)
        gemm_hmma_k<64, 128, 2, 4, false><<<grid, 256, SMEM_L2>>>(
            a2h, w2hi, b2, out, DOUT, 0, nullptr);
    }
}

// round 17
// speedup vs baseline: 1.1234x; 1.0102x over previous
#include <cuda_runtime.h>
#include <cuda_fp16.h>
#include <cstdint>

// Problem constants
#define N1_SRC 495616
#define N1_DST 45056
#define E1     450560
#define N2_SRC 45056
#define N2_DST 4096
#define E2     40960
#define D      512
#define DOUT   256

// ---------------- device scratch ----------------
__device__ __half g_h1h[(size_t)N1_DST * D];          // layer-1 output (fp16, compact)
__device__ __half g_a1h[(size_t)N1_DST * D];          // layer-1 A (fp16, compact)
__device__ __half g_a2h[(size_t)N2_DST * D];          // layer-2 A (single fp16)
__device__ __half g_w1hi[(size_t)D * D];              // W1^T [N=512,K=512] fp16
__device__ __half g_w2hi[(size_t)DOUT * D];           // W2^T [N=256,K=512] fp16

// cnt1 | cnt2 | used  (one memset)
__device__ int g_cnt[N1_DST + N2_DST + N1_DST];
__device__ int g_cur[N1_DST + N2_DST];
__device__ int g_off1[N1_DST + 1];
__device__ int g_srt1[E1];
__device__ int g_off2[N2_DST + 1];
__device__ int g_srt2[E2];                             // stores REMAPPED src ids
__device__ int g_remap[N1_DST + 1];
__device__ int g_ulist[N1_DST];
__device__ int g_ucnt[1];

// ---------------- PTX helpers (base-target safe) ----------------
__device__ __forceinline__ uint32_t smem_u32(const void* p) {
    uint32_t a;
    asm("{ .reg .u64 t; cvta.to.shared.u64 t, %1; cvt.u32.u64 %0, t; }" : "=r"(a) : "l"(p));
    return a;
}
__device__ __forceinline__ void cp16(uint32_t s, const void* g) {
    asm volatile("cp.async.cg.shared.global [%0], [%1], 16;" :: "r"(s), "l"(g));
}
__device__ __forceinline__ void cp_commit() {
    asm volatile("cp.async.commit_group;" ::: "memory");
}
template <int N>
__device__ __forceinline__ void cp_wait() {
    asm volatile("cp.async.wait_group %0;" :: "n"(N) : "memory");
}
__device__ __forceinline__ void ldm_x4(uint32_t* r, uint32_t addr) {
    asm volatile("ldmatrix.sync.aligned.m8n8.x4.shared.b16 {%0,%1,%2,%3}, [%4];"
                 : "=r"(r[0]), "=r"(r[1]), "=r"(r[2]), "=r"(r[3]) : "r"(addr));
}
// D += A(f16) * B(f16), m16n8k16, fp32 accum
__device__ __forceinline__ void mma_f16(float* c, const uint32_t* a, const uint32_t* b) {
    asm volatile(
        "mma.sync.aligned.m16n8k16.row.col.f32.f16.f16.f32 "
        "{%0,%1,%2,%3}, {%4,%5,%6,%7}, {%8,%9}, {%0,%1,%2,%3};"
        : "+f"(c[0]), "+f"(c[1]), "+f"(c[2]), "+f"(c[3])
        : "r"(a[0]), "r"(a[1]), "r"(a[2]), "r"(a[3]), "r"(b[0]), "r"(b[1]));
}

// ---------------- fused prep: hist + used-marks + weight conversion ----------------
#define PREP_N (E1 + E2 + N2_DST + D * D + DOUT * D)

__global__ void prep_k(const int* __restrict__ ed1, const int* __restrict__ ed2,
                       const int* __restrict__ es2, int* __restrict__ cnt,
                       const float* __restrict__ W1, __half* __restrict__ t1,
                       const float* __restrict__ W2, __half* __restrict__ t2) {
    int* used = cnt + (N1_DST + N2_DST);
    int i = blockIdx.x * blockDim.x + threadIdx.x;
    if (i < E1) {
        atomicAdd(&cnt[ed1[i]], 1);
    } else if (i < E1 + E2) {
        int j = i - E1;
        atomicAdd(&cnt[N1_DST + ed2[j]], 1);
        used[es2[j]] = 1;                 // benign race, deterministic
    } else if (i < E1 + E2 + N2_DST) {
        used[i - E1 - E2] = 1;            // self rows 0..4095
    } else {
        int j = i - (E1 + E2 + N2_DST);
        if (j < D * D) {
            int n = j / D, k = j - n * D;
            t1[j] = __float2half_rn(W1[(size_t)k * D + n]);
        } else if (j < D * D + DOUT * D) {
            j -= D * D;
            int n = j / D, k = j - n * D;
            t2[j] = __float2half_rn(W2[(size_t)k * DOUT + n]);
        }
    }
}

// block 0: cnt1->off1/cur ; block 1: cnt2->off2/cur+N1 ; block 2: used->remap,+ucnt
__global__ void scan_all_k(const int* __restrict__ cnt, int* __restrict__ cur,
                           int* __restrict__ off1, int* __restrict__ off2,
                           int* __restrict__ remap, int* __restrict__ ucnt) {
    const int* c; int* cu; int* off; int n;
    if (blockIdx.x == 0)      { c = cnt;                    cu = cur;           off = off1;  n = N1_DST; }
    else if (blockIdx.x == 1) { c = cnt + N1_DST;           cu = cur + N1_DST;  off = off2;  n = N2_DST; }
    else                      { c = cnt + N1_DST + N2_DST;  cu = nullptr;       off = remap; n = N1_DST; }

    __shared__ int wsum[32];
    __shared__ int carry_s;
    int tid = threadIdx.x, lane = tid & 31, w = tid >> 5;
    if (tid == 0) carry_s = 0;
    __syncthreads();
    for (int base = 0; base < n; base += 4096) {
        int i = base + tid * 4;
        int4 v = *(const int4*)&c[i];
        int s = v.x + v.y + v.z + v.w;
        int x = s;
#pragma unroll
        for (int st = 1; st < 32; st <<= 1) {
            int t = __shfl_up_sync(0xFFFFFFFFu, x, st);
            if (lane >= st) x += t;
        }
        if (lane == 31) wsum[w] = x;
        __syncthreads();
        if (w == 0) {
            int y = wsum[lane];
#pragma unroll
            for (int st = 1; st < 32; st <<= 1) {
                int t = __shfl_up_sync(0xFFFFFFFFu, y, st);
                if (lane >= st) y += t;
            }
            wsum[lane] = y;
        }
        __syncthreads();
        int excl = carry_s + (w ? wsum[w - 1] : 0) + x - s;   // exclusive prefix of item 0
        int4 o;
        o.x = excl;
        o.y = excl + v.x;
        o.z = excl + v.x + v.y;
        o.w = excl + v.x + v.y + v.z;
        *(int4*)&off[i] = o;
        if (cu) *(int4*)&cu[i] = o;
        __syncthreads();
        if (tid == 1023) carry_s = excl + s;
        __syncthreads();
    }
    if (threadIdx.x == 0) {
        off[n] = carry_s;
        if (blockIdx.x == 2) ucnt[0] = carry_s;
    }
}

// scatter both edge lists (layer-2 sources remapped) + build used_list
__global__ void scatter_all_k(const int* __restrict__ es1, const int* __restrict__ ed1,
                              const int* __restrict__ es2, const int* __restrict__ ed2,
                              int* __restrict__ cur, const int* __restrict__ cnt,
                              const int* __restrict__ remap,
                              int* __restrict__ srt1, int* __restrict__ srt2,
                              int* __restrict__ ulist) {
    const int* used = cnt + (N1_DST + N2_DST);
    int i = blockIdx.x * blockDim.x + threadIdx.x;
    if (i < E1) {
        int p = atomicAdd(&cur[ed1[i]], 1);
        srt1[p] = es1[i];
    } else if (i < E1 + E2) {
        int j = i - E1;
        int p = atomicAdd(&cur[N1_DST + ed2[j]], 1);
        srt2[p] = remap[es2[j]];          // remapped into compact h1 space
    } else if (i < E1 + E2 + N1_DST) {
        int k = i - E1 - E2;
        if (used[k]) ulist[remap[k]] = k;
    }
}

// ---------------- layer-1 aggregation: 2 used nodes per 256-thread CTA ----------------
__global__ void __launch_bounds__(256)
agg1_k(const float* __restrict__ feat, const int* __restrict__ off,
       const int* __restrict__ srt, const int* __restrict__ ulist,
       const int* __restrict__ ucnt, __half* __restrict__ ahi) {
    int b = blockIdx.x * 2 + (threadIdx.x >> 7);
    if (b >= ucnt[0]) return;
    int node = ulist[b];
    int t = threadIdx.x & 127;            // covers cols t*4 .. t*4+3
    const float4* fp = (const float4*)feat;
    int bg = off[node], e = off[node + 1];

    float4 acc = fp[(size_t)node * (D / 4) + t];
    int j = bg;
    for (; j + 3 < e; j += 4) {
        int s0 = srt[j], s1 = srt[j + 1], s2 = srt[j + 2], s3 = srt[j + 3];
        float4 v0 = fp[(size_t)s0 * (D / 4) + t];
        float4 v1 = fp[(size_t)s1 * (D / 4) + t];
        float4 v2 = fp[(size_t)s2 * (D / 4) + t];
        float4 v3 = fp[(size_t)s3 * (D / 4) + t];
        acc.x += v0.x + v1.x + v2.x + v3.x;
        acc.y += v0.y + v1.y + v2.y + v3.y;
        acc.z += v0.z + v1.z + v2.z + v3.z;
        acc.w += v0.w + v1.w + v2.w + v3.w;
    }
    for (; j < e; j++) {
        int s0 = srt[j];
        float4 v0 = fp[(size_t)s0 * (D / 4) + t];
        acc.x += v0.x; acc.y += v0.y; acc.z += v0.z; acc.w += v0.w;
    }
    float sc = 1.0f / (float)(e - bg + 1);
    __half2 p01 = __floats2half2_rn(acc.x * sc, acc.y * sc);
    __half2 p23 = __floats2half2_rn(acc.z * sc, acc.w * sc);
    uint2 o;
    o.x = *(uint32_t*)&p01;
    o.y = *(uint32_t*)&p23;
    ((uint2*)ahi)[(size_t)b * (D / 4) + t] = o;       // compact row b
}

// ---------------- layer-2 aggregation: 2 nodes per 256-thread CTA, fp16 gather ----------------
__global__ void __launch_bounds__(256)
agg2_k(const __half* __restrict__ feat, const int* __restrict__ off,
       const int* __restrict__ srt, const int* __restrict__ remap,
       __half* __restrict__ ah) {
    int node = blockIdx.x * 2 + (threadIdx.x >> 7);
    int t = threadIdx.x & 127;            // covers cols t*4 .. t*4+3
    const uint2* fp = (const uint2*)feat;
    int b = off[node], e = off[node + 1];

    uint2 sv = fp[(size_t)remap[node] * (D / 4) + t];   // self row (remapped)
    float2 f01 = __half22float2(*(__half2*)&sv.x);
    float2 f23 = __half22float2(*(__half2*)&sv.y);
    float a0 = f01.x, a1 = f01.y, a2 = f23.x, a3 = f23.y;

    int j = b;
    for (; j + 1 < e; j += 2) {
        uint2 v0 = fp[(size_t)srt[j] * (D / 4) + t];
        uint2 v1 = fp[(size_t)srt[j + 1] * (D / 4) + t];
        float2 u0 = __half22float2(*(__half2*)&v0.x);
        float2 u1 = __half22float2(*(__half2*)&v0.y);
        float2 w0 = __half22float2(*(__half2*)&v1.x);
        float2 w1 = __half22float2(*(__half2*)&v1.y);
        a0 += u0.x + w0.x; a1 += u0.y + w0.y;
        a2 += u1.x + w1.x; a3 += u1.y + w1.y;
    }
    if (j < e) {
        uint2 v0 = fp[(size_t)srt[j] * (D / 4) + t];
        float2 u0 = __half22float2(*(__half2*)&v0.x);
        float2 u1 = __half22float2(*(__half2*)&v0.y);
        a0 += u0.x; a1 += u0.y; a2 += u1.x; a3 += u1.y;
    }
    float sc = 1.0f / (float)(e - b + 1);
    __half2 p01 = __floats2half2_rn(a0 * sc, a1 * sc);
    __half2 p23 = __floats2half2_rn(a2 * sc, a3 * sc);
    uint2 o;
    o.x = *(uint32_t*)&p01;
    o.y = *(uint32_t*)&p23;
    ((uint2*)ah)[(size_t)node * (D / 4) + t] = o;
}

// ---------------- HMMA fp16 GEMM (BK=128, templated) ----------------
// C = Ah*Bh + bias, opt relu. HOUT: fp16 out. mcount: optional M early-exit bound.
// Row = 128 fp16 = 256B data + 16B pad = 272B (68 words => 4-bank shift/row, conflict-free).
#define ROWB 272

template <int BM, int BN, int TM, int TN, bool HOUT>
__global__ void __launch_bounds__(TM * TN * 32, 1)
gemm_hmma_k(const __half* __restrict__ Ah, const __half* __restrict__ Bh,
            const float* __restrict__ bias, void* __restrict__ Cv,
            int ldc, int relu, const int* __restrict__ mcount) {
    constexpr int THREADS = TM * TN * 32;
    constexpr int WM = BM / TM;
    constexpr int WN = BN / TN;
    constexpr int MT = WM / 16;
    constexpr int NG = WN / 16;
    constexpr int NT = WN / 8;
    constexpr int TOTROWS = BM + BN;
    constexpr int STAGE = TOTROWS * ROWB;
    constexpr int OPS = TOTROWS * 16 / THREADS;  // 16 x 16B per 256B row

    int m0 = blockIdx.y * BM;
    if (mcount && m0 >= mcount[0]) return;   // dead tile: rows unused downstream

    extern __shared__ char smem[];
    uint32_t sm = smem_u32(smem);
    int tid = threadIdx.x;
    int wid = tid >> 5, lane = tid & 31;
    int wm = wid % TM;
    int wn = wid / TM;
    int n0 = blockIdx.x * BN;

    const char* gAh = (const char*)(Ah + (size_t)m0 * D);
    const char* gBh = (const char*)(Bh + (size_t)n0 * D);

    auto issue = [&](uint32_t st, int kc) {
#pragma unroll
        for (int j = 0; j < OPS; j++) {
            int i = tid + j * THREADS;
            int g = i >> 4;
            int c16 = i & 15;
            const char* src = (g < BM) ? gAh + (size_t)g * (D * 2)
                                       : gBh + (size_t)(g - BM) * (D * 2);
            cp16(st + g * ROWB + c16 * 16, src + kc * 256 + c16 * 16);
        }
        cp_commit();
    };

    float acc[MT][NT][4];
#pragma unroll
    for (int mt = 0; mt < MT; mt++)
#pragma unroll
        for (int nt = 0; nt < NT; nt++)
#pragma unroll
            for (int r = 0; r < 4; r++) acc[mt][nt][r] = 0.0f;

    const int NCH = D / 128;              // 4
    issue(sm, 0);

    int a_row = wm * WM + (lane & 15);
    int a_kb = (lane >> 4) * 16;
    int b_row = wn * WN + ((lane >> 4) & 1) * 8 + (lane & 7);
    int b_kb = ((lane >> 3) & 1) * 16;

    for (int c = 0; c < NCH; c++) {
        uint32_t st = sm + (c & 1) * STAGE;
        if (c + 1 < NCH) {
            issue(sm + ((c + 1) & 1) * STAGE, c + 1);
            cp_wait<1>();
        } else {
            cp_wait<0>();
        }
        __syncthreads();

        uint32_t sAh = st;
        uint32_t sBh = st + BM * ROWB;

#pragma unroll
        for (int kk = 0; kk < 8; kk++) {
            uint32_t ah[MT][4];
#pragma unroll
            for (int mt = 0; mt < MT; mt++)
                ldm_x4(ah[mt], sAh + (a_row + mt * 16) * ROWB + kk * 32 + a_kb);
#pragma unroll
            for (int ng = 0; ng < NG; ng++) {
                uint32_t bh[4];
                ldm_x4(bh, sBh + (b_row + ng * 16) * ROWB + kk * 32 + b_kb);
#pragma unroll
                for (int mt = 0; mt < MT; mt++) {
#pragma unroll
                    for (int hf = 0; hf < 2; hf++)
                        mma_f16(acc[mt][ng * 2 + hf], ah[mt], &bh[hf * 2]);
                }
            }
        }
        __syncthreads();
    }

    // epilogue
#pragma unroll
    for (int mt = 0; mt < MT; mt++) {
        int row0 = m0 + wm * WM + mt * 16 + (lane >> 2);
#pragma unroll
        for (int nt = 0; nt < NT; nt++) {
            int col = n0 + wn * WN + nt * 8 + (lane & 3) * 2;
            float b0 = bias[col], b1 = bias[col + 1];
            float2 v0, v1;
            v0.x = acc[mt][nt][0] + b0; v0.y = acc[mt][nt][1] + b1;
            v1.x = acc[mt][nt][2] + b0; v1.y = acc[mt][nt][3] + b1;
            if (relu) {
                v0.x = fmaxf(v0.x, 0.f); v0.y = fmaxf(v0.y, 0.f);
                v1.x = fmaxf(v1.x, 0.f); v1.y = fmaxf(v1.y, 0.f);
            }
            if (HOUT) {
                __half* Ch = (__half*)Cv;
                __half2 o0 = __floats2half2_rn(v0.x, v0.y);
                __half2 o1 = __floats2half2_rn(v1.x, v1.y);
                *(__half2*)&Ch[(size_t)row0 * ldc + col] = o0;
                *(__half2*)&Ch[(size_t)(row0 + 8) * ldc + col] = o1;
            } else {
                float* C = (float*)Cv;
                *(float2*)&C[(size_t)row0 * ldc + col] = v0;
                *(float2*)&C[(size_t)(row0 + 8) * ldc + col] = v1;
            }
        }
    }
}

// L1: 128x256 tile, 512 threads, fp16 out.  smem = 2*(128+256)*272 = 208896
// L2: 64x128 tile, 256 threads, fp32 out.   smem = 2*(64+128)*272 = 104448
#define SMEM_L1 (2 * (128 + 256) * ROWB)
#define SMEM_L2 (2 * (64 + 128) * ROWB)

// ---------------- launch (single stream) ----------------
extern "C" void kernel_launch(void* const* d_in, const int* in_sizes, int n_in,
                              void* d_out, int out_size) {
    const float* feats = (const float*)d_in[0];
    const float* W1    = (const float*)d_in[1];
    const float* b1    = (const float*)d_in[2];
    const float* W2    = (const float*)d_in[3];
    const float* b2    = (const float*)d_in[4];
    const int*   es1   = (const int*)d_in[5];
    const int*   ed1   = (const int*)d_in[6];
    const int*   es2   = (const int*)d_in[7];
    const int*   ed2   = (const int*)d_in[8];
    float* out = (float*)d_out;

    __half *h1h, *a1h, *a2h, *w1hi, *w2hi;
    int *cnt, *cur, *off1, *srt1, *off2, *srt2, *remap, *ulist, *ucnt;
    cudaGetSymbolAddress((void**)&h1h,   g_h1h);
    cudaGetSymbolAddress((void**)&a1h,   g_a1h);
    cudaGetSymbolAddress((void**)&a2h,   g_a2h);
    cudaGetSymbolAddress((void**)&w1hi,  g_w1hi);
    cudaGetSymbolAddress((void**)&w2hi,  g_w2hi);
    cudaGetSymbolAddress((void**)&cnt,   g_cnt);
    cudaGetSymbolAddress((void**)&cur,   g_cur);
    cudaGetSymbolAddress((void**)&off1,  g_off1);
    cudaGetSymbolAddress((void**)&srt1,  g_srt1);
    cudaGetSymbolAddress((void**)&off2,  g_off2);
    cudaGetSymbolAddress((void**)&srt2,  g_srt2);
    cudaGetSymbolAddress((void**)&remap, g_remap);
    cudaGetSymbolAddress((void**)&ulist, g_ulist);
    cudaGetSymbolAddress((void**)&ucnt,  g_ucnt);

    cudaFuncSetAttribute((void*)gemm_hmma_k<128, 256, 4, 4, true>,
                         cudaFuncAttributeMaxDynamicSharedMemorySize, SMEM_L1);
    cudaFuncSetAttribute((void*)gemm_hmma_k<64, 128, 2, 4, false>,
                         cudaFuncAttributeMaxDynamicSharedMemorySize, SMEM_L2);

    // ---- fused prep: memset -> (hist + used-marks + weight conversion) -> scan -> scatter ----
    cudaMemsetAsync(cnt, 0, (2 * N1_DST + N2_DST) * sizeof(int));
    prep_k<<<(PREP_N + 255) / 256, 256>>>(ed1, ed2, es2, cnt, W1, w1hi, W2, w2hi);
    scan_all_k<<<3, 1024>>>(cnt, cur, off1, off2, remap, ucnt);
    scatter_all_k<<<(E1 + E2 + N1_DST + 255) / 256, 256>>>(
        es1, ed1, es2, ed2, cur, cnt, remap, srt1, srt2, ulist);

    // ---- layer 1 (only used rows, compact) ----
    agg1_k<<<N1_DST / 2, 256>>>(feats, off1, srt1, ulist, ucnt, a1h);
    {
        dim3 grid(D / 256, N1_DST / 128);   // (2, 352); dead M-tiles exit early
        gemm_hmma_k<128, 256, 4, 4, true><<<grid, 512, SMEM_L1>>>(
            a1h, w1hi, b1, h1h, D, 1, ucnt);
    }

    // ---- layer 2 ----
    agg2_k<<<N2_DST / 2, 256>>>(h1h, off2, srt2, remap, a2h);
    {
        dim3 grid(DOUT / 128, N2_DST / 64);  // (2, 64)
        gemm_hmma_k<64, 128, 2, 4, false><<<grid, 256, SMEM_L2>>>(
            a2h, w2hi, b2, out, DOUT, 0, nullptr);
    }
}